// round 13
// baseline (speedup 1.0000x reference)
#include <cuda_runtime.h>
#include <math.h>

#define NB 32
#define SDIM 256
#define SS 65536            // SDIM*SDIM
#define TOT (NB*SS)

#define T_FOV 0.08748866352592401f   // tan(10/360*pi)
#define EPSV 1e-7f
#define ONE_M_EPS 0.99999990f        // float(1.0 - 1e-7)
#define INV_GAMMA 0.45454545454545453f
#define GAMMA_F 2.2f
#define P1_STEPS 4                   // phase-1 cap (one branchless chunk of 4)
#define P2_STEPS 16                  // phase-2 cap (steps 5..16)
#define WSC (128.0f / T_FOV)         // pixel-projection scale

// Scratch (no allocations allowed)
static __device__ float g_params[NB * 8];   // la, lb, spec_alpha, spec_strength, ldx, ldy, ldz, eps^alpha
static __device__ int   g_min_bits[NB];     // min depth as positive-float bits
static __device__ float g_shadow[TOT];
static __device__ float4 g_quad[TOT];       // (v00, v01, v10, v11) border-clamped, 32MB
static __device__ int   g_queueA[TOT];      // survivors after 4 steps
static __device__ int   g_queueB[TOT];      // survivors after 16 steps
static __device__ int   g_qcountA;
static __device__ int   g_qcountB;

// Normalized 1D Gaussian weights (ksize=7, sigma=2); separable form of the
// reference's outer(g,g)/sum 2D kernel.
__constant__ float GW[7] = {0.07015933f, 0.13107488f, 0.19071282f,
                            0.21610594f,
                            0.19071282f, 0.13107488f, 0.07015933f};

__global__ void params_kernel(const float* __restrict__ netL,
                              const float* __restrict__ light) {
    int b = threadIdx.x;
    if (b == 0) { g_qcountA = 0; g_qcountB = 0; }
    if (b >= NB) return;
    float t0 = tanhf(netL[b * 6 + 0]);
    float t1 = tanhf(netL[b * 6 + 1]);
    float t2 = tanhf(netL[b * 6 + 2]);
    float t5 = tanhf(netL[b * 6 + 5]);
    const float t_alpha = 10.313708498984761f;   // sqrt(128) - 1
    float sa = (t0 * 0.5f + 0.5f) * t_alpha + 1.0f;
    float spec_alpha = sa * sa;
    float* p = g_params + b * 8;
    p[0] = t1 * 0.5f + 0.5f;                  // light_a
    p[1] = t2 * 0.5f + 0.5f;                  // light_b
    p[2] = spec_alpha;
    p[3] = (t5 * 0.5f + 0.5f) * 0.5f;         // spec_strength
    float lx = light[b * 2 + 0];
    float ly = light[b * 2 + 1];
    float n = sqrtf(lx * lx + ly * ly + 1.0f);
    p[4] = lx / n;
    p[5] = ly / n;
    p[6] = 1.0f / n;
    p[7] = __powf(EPSV, spec_alpha);          // spec_sh when spec clamps to EPS
    g_min_bits[b] = 0x7f7fffff;               // +FLT_MAX bits
}

// Build bilinear quad image + per-batch min-depth (positive-float atomicMin).
__global__ void __launch_bounds__(256) quad_kernel(const float* __restrict__ depth) {
    int idx = blockIdx.x * 256 + threadIdx.x;
    int b = idx >> 16;
    int p = idx & (SS - 1);
    int y = p >> 8;
    int x = p & 255;
    const float* dimg = depth + b * SS;
    int x1 = min(x + 1, 255);
    int y1 = min(y + 1, 255);
    float4 q;
    q.x = __ldg(dimg + y  * SDIM + x);
    q.y = __ldg(dimg + y  * SDIM + x1);
    q.z = __ldg(dimg + y1 * SDIM + x);
    q.w = __ldg(dimg + y1 * SDIM + x1);
    g_quad[idx] = q;

    float m = q.x;
    #pragma unroll
    for (int s = 16; s > 0; s >>= 1)
        m = fminf(m, __shfl_xor_sync(0xffffffffu, m, s));
    __shared__ float warp_min[8];
    if ((threadIdx.x & 31) == 0) warp_min[threadIdx.x >> 5] = m;
    __syncthreads();
    if (threadIdx.x == 0) {
        float bm = warp_min[0];
        #pragma unroll
        for (int w = 1; w < 8; w++) bm = fminf(bm, warp_min[w]);
        atomicMin(&g_min_bits[b], __float_as_int(bm));   // valid: all positive
    }
}

// Per-ray setup shared by all march kernels.
struct Ray {
    float d, sz, sxW, syW, pxW0, pyW0, nf;
};
__device__ __forceinline__ Ray ray_setup(int idx) {
    int b = idx >> 16;
    int p = idx & (SS - 1);
    int i = p >> 8;
    int j = p & 255;
    float d = __ldg(&g_quad[idx].x);            // quad.x == depth[p]
    float ci = __fmul_rn(__fadd_rn(__fmul_rn((float)i, 2.0f / 255.0f), -1.0f), T_FOV);
    float cj = __fmul_rn(__fadd_rn(__fmul_rn((float)j, 2.0f / 255.0f), -1.0f), T_FOV);
    const float* prm = g_params + b * 8;
    Ray r;
    r.d = d;
    float sx = -prm[4] * (1.0f / 256.0f);
    float sy = -prm[5] * (1.0f / 256.0f);
    r.sz = -prm[6] * (1.0f / 256.0f);           // strictly negative
    r.sxW = sx * WSC;
    r.syW = sy * WSC;
    r.pxW0 = cj * d * WSC;
    r.pyW0 = ci * d * WSC;
    float minz = __int_as_float(g_min_bits[idx >> 16]) - 1e-5f;
    // Steps with pz >= minz: any bilinear sample is a convex combination of
    // depths >= min_depth, so shadow is impossible once pz < minz.
    r.nf = fminf(floorf((d - minz) * __fdividef(-1.0f, r.sz)), 256.0f);
    return r;
}

// N march steps kk = kb..kb+N-1 (no n-clamp: steps past n provably cannot
// produce a false hit — pzz < minz <= all depths — and coords are
// NaN/overflow-safe via the [0,255] clamp). One RCP at the chunk center;
// rz via 3rd-order Horner (|e| <= (N/2)*0.0075, trunc error negligible).
template <int N>
__device__ __forceinline__ bool marchN(float kb, const Ray& r,
                                       const float4* __restrict__ quad) {
    float mid = 0.5f * (float)(N - 1);
    float pzm = fmaf(kb + mid, r.sz, r.d);
    float rzm = __fdividef(1.0f, pzm);
    float c = r.sz * rzm;
    bool hit = false;
    #pragma unroll
    for (int u = 0; u < N; u++) {
        float kk = kb + (float)u;               // compile-time offset
        float e = ((float)u - mid) * c;
        float t1 = 1.0f - e;
        float t2 = fmaf(-e, t1, 1.0f);
        float pl = fmaf(-e, t2, 1.0f);          // 1 - e + e^2 - e^3
        float rz = rzm * pl;
        float pzz = fmaf(kk, r.sz, r.d);
        float x = fmaf(fmaf(kk, r.sxW, r.pxW0), rz, 127.5f);
        float y = fmaf(fmaf(kk, r.syW, r.pyW0), rz, 127.5f);
        x = fminf(fmaxf(x, 0.0f), 255.0f);      // also maps NaN -> 0
        y = fminf(fmaxf(y, 0.0f), 255.0f);
        int x0i = __float2int_rd(x);
        int y0i = __float2int_rd(y);
        float wx = x - (float)x0i;
        float wy = y - (float)y0i;
        float4 q = __ldg(quad + y0i * SDIM + x0i);
        float top = fmaf(wx, q.y - q.x, q.x);
        float bot = fmaf(wx, q.w - q.z, q.z);
        float sampled = fmaf(wy, bot - top, top);
        hit |= (sampled < pzz);
    }
    return hit;
}

__device__ __forceinline__ void queue_push(bool surv, int idx,
                                           int* __restrict__ queue,
                                           int* __restrict__ count) {
    unsigned mask = __ballot_sync(0xffffffffu, surv);
    if (mask) {
        int lane = threadIdx.x & 31;
        int leader = __ffs(mask) - 1;
        int base = 0;
        if (lane == leader) base = atomicAdd(count, __popc(mask));
        base = __shfl_sync(0xffffffffu, base, leader);
        if (surv) queue[base + __popc(mask & ((1u << lane) - 1u))] = idx;
    }
}

// Phase 1: branchless 4-step march; survivors -> queue A.
__global__ void __launch_bounds__(256) shadow1_kernel() {
    int idx = blockIdx.x * blockDim.x + threadIdx.x;
    const float4* quad = g_quad + (idx & ~(SS - 1));
    Ray r = ray_setup(idx);
    bool hit = marchN<4>(1.0f, r, quad);
    g_shadow[idx] = hit ? 1.0f : 0.0f;
    bool surv = !hit && (r.nf > (float)P1_STEPS);
    queue_push(surv, idx, g_queueA, &g_qcountA);
}

// Phase 2: dense march of queue-A rays, steps 5..16; survivors -> queue B.
__global__ void __launch_bounds__(256) shadow2_kernel() {
    int total = g_qcountA;
    for (int q = blockIdx.x * blockDim.x + threadIdx.x; q < total;
         q += gridDim.x * blockDim.x) {
        int idx = g_queueA[q];
        const float4* quad = g_quad + (idx & ~(SS - 1));
        Ray r = ray_setup(idx);
        bool hit = marchN<4>(5.0f, r, quad);
        hit     |= marchN<4>(9.0f, r, quad);
        hit     |= marchN<4>(13.0f, r, quad);
        if (hit) g_shadow[idx] = 1.0f;
        bool surv = !hit && (r.nf > (float)P2_STEPS);
        queue_push(surv, idx, g_queueB, &g_qcountB);
    }
}

// Phase 3: dense march of queue-B rays from k = 17, exit check every 16 steps.
__global__ void __launch_bounds__(256) shadow3_kernel() {
    int total = g_qcountB;
    for (int q = blockIdx.x * blockDim.x + threadIdx.x; q < total;
         q += gridDim.x * blockDim.x) {
        int idx = g_queueB[q];
        const float4* quad = g_quad + (idx & ~(SS - 1));
        Ray r = ray_setup(idx);
        bool hit = false;
        for (float kb = (float)(P2_STEPS + 1); kb <= r.nf && !hit; kb += 16.0f) {
            hit  = marchN<8>(kb,        r, quad);
            hit |= marchN<8>(kb + 8.0f, r, quad);
        }
        if (hit) g_shadow[idx] = 1.0f;
    }
}

// Fused: 7x7 separable Gaussian blur of shadow (smem tile) + Phong epilogue.
__global__ void __launch_bounds__(1024) final_kernel(const float* __restrict__ netA,
                                                     const float* __restrict__ normal,
                                                     float* __restrict__ out) {
    __shared__ float s_sh[38][40];
    __shared__ float s_hb[38][33];

    int b = blockIdx.z;
    int ti0 = blockIdx.y * 32;
    int tj0 = blockIdx.x * 32;
    int tx = threadIdx.x;
    int ty = threadIdx.y;
    int tid = ty * 32 + tx;

    const float* shb = g_shadow + b * SS;

    for (int t = tid; t < 38 * 38; t += 1024) {
        int r = t / 38;
        int c = t - r * 38;
        int gi = ti0 - 3 + r;
        int gj = tj0 - 3 + c;
        float v = 0.0f;
        if (gi >= 0 && gi < SDIM && gj >= 0 && gj < SDIM) v = shb[gi * SDIM + gj];
        s_sh[r][c] = v;
    }
    __syncthreads();

    for (int t = tid; t < 38 * 32; t += 1024) {
        int r = t >> 5;
        int c = t & 31;
        float acc = 0.0f;
        #pragma unroll
        for (int dj = 0; dj < 7; dj++) acc += GW[dj] * s_sh[r][c + dj];
        s_hb[r][c] = acc;
    }
    __syncthreads();

    float ssum = 0.0f;
    #pragma unroll
    for (int dy = 0; dy < 7; dy++) ssum += GW[dy] * s_hb[ty + dy][tx];
    float shadow_factor = fminf(fmaxf(1.0f - ssum, 0.1f), 1.0f);

    int i = ti0 + ty;
    int j = tj0 + tx;
    int p = i * SDIM + j;

    const float* prm = g_params + b * 8;
    float la = prm[0], lb = prm[1], spec_alpha = prm[2], spec_strength = prm[3];
    float ldx = prm[4], ldy = prm[5], ldz = prm[6], eps_pow = prm[7];

    const float* nb = normal + b * 3 * SS;
    float nx = __ldg(nb + p);
    float ny = __ldg(nb + SS + p);
    float nz = __ldg(nb + 2 * SS + p);

    float cosb = nx * ldx + ny * ldy + nz * ldz;
    float diffuse = fmaxf(cosb, 0.0f);

    float aj = __fmul_rn(__fadd_rn(__fmul_rn((float)(255 - j), 2.0f / 255.0f), -1.0f), T_FOV);
    float ai = __fmul_rn(__fadd_rn(__fmul_rn((float)(255 - i), 2.0f / 255.0f), -1.0f), T_FOV);
    float rnrm = rsqrtf(ai * ai + aj * aj + 1.0f);
    float vdx = aj * rnrm, vdy = ai * rnrm, vdz = rnrm;

    float rdx = 2.0f * cosb * nx - ldx;
    float rdy = 2.0f * cosb * ny - ldy;
    float rdz = 2.0f * cosb * nz - ldz;

    float mask = (i >= 5 && i < SDIM - 5 && j >= 5 && j < SDIM - 5) ? 1.0f : 0.0f;
    float spec = fmaxf(vdx * rdx + vdy * rdy + vdz * rdz, 0.0f)
               * ((cosb > 0.0f) ? 1.0f : 0.0f) * mask;
    float spec_sh = (spec > EPSV)
                  ? __powf(fminf(spec, ONE_M_EPS), spec_alpha)
                  : eps_pow;

    float shading = la + lb * diffuse * shadow_factor;
    float term2 = spec_strength * lb * spec_sh;

    const float NLOG2E2 = -2.8853900817779268f;   // -2*log2(e)
    const float* ab = netA + b * 5 * SS;
    float* ob = out + b * 3 * SS;
    #pragma unroll
    for (int c = 0; c < 3; c++) {
        float a = __ldg(ab + c * SS + p);
        float u = exp2f(a * NLOG2E2);
        float alb = exp2f(-GAMMA_F * __log2f(1.0f + u));
        float r = alb * shading + term2;
        ob[c * SS + p] = __powf(fmaxf(r, EPSV), INV_GAMMA);
    }
}

extern "C" void kernel_launch(void* const* d_in, const int* in_sizes, int n_in,
                              void* d_out, int out_size) {
    const float* netA   = (const float*)d_in[0];
    const float* netL   = (const float*)d_in[1];
    const float* normal = (const float*)d_in[2];
    const float* depth  = (const float*)d_in[3];
    const float* light  = (const float*)d_in[4];
    float* out = (float*)d_out;

    params_kernel<<<1, 32>>>(netL, light);
    quad_kernel<<<TOT / 256, 256>>>(depth);
    shadow1_kernel<<<TOT / 256, 256>>>();
    shadow2_kernel<<<1184, 256>>>();   // dense survivors, grid-stride
    shadow3_kernel<<<1184, 256>>>();
    dim3 grid(SDIM / 32, SDIM / 32, NB);
    dim3 blk(32, 32);
    final_kernel<<<grid, blk>>>(netA, normal, out);
}

// round 14
// speedup vs baseline: 1.0258x; 1.0258x over previous
#include <cuda_runtime.h>
#include <math.h>

#define NB 32
#define SDIM 256
#define SS 65536            // SDIM*SDIM
#define TOT (NB*SS)

#define T_FOV 0.08748866352592401f   // tan(10/360*pi)
#define EPSV 1e-7f
#define ONE_M_EPS 0.99999990f        // float(1.0 - 1e-7)
#define INV_GAMMA 0.45454545454545453f
#define GAMMA_F 2.2f
#define P1_STEPS 16                  // phase-1 cap (8 + 8 with warp-uniform mid-check)
#define WSC (128.0f / T_FOV)         // pixel-projection scale

// Scratch (no allocations allowed)
static __device__ float g_params[NB * 8];   // la, lb, spec_alpha, spec_strength, ldx, ldy, ldz, eps^alpha
static __device__ int   g_min_bits[NB];     // min depth as positive-float bits
static __device__ float g_shadow[TOT];
static __device__ float4 g_quad[TOT];       // (v00, v01, v10, v11) border-clamped, 32MB
static __device__ int   g_queueA[TOT];      // per-batch survivor queues (segment b*SS)
static __device__ int   g_qcountA[NB];

// Normalized 1D Gaussian weights (ksize=7, sigma=2); separable form of the
// reference's outer(g,g)/sum 2D kernel.
__constant__ float GW[7] = {0.07015933f, 0.13107488f, 0.19071282f,
                            0.21610594f,
                            0.19071282f, 0.13107488f, 0.07015933f};

__global__ void params_kernel(const float* __restrict__ netL,
                              const float* __restrict__ light) {
    int b = threadIdx.x;
    if (b >= NB) return;
    g_qcountA[b] = 0;
    float t0 = tanhf(netL[b * 6 + 0]);
    float t1 = tanhf(netL[b * 6 + 1]);
    float t2 = tanhf(netL[b * 6 + 2]);
    float t5 = tanhf(netL[b * 6 + 5]);
    const float t_alpha = 10.313708498984761f;   // sqrt(128) - 1
    float sa = (t0 * 0.5f + 0.5f) * t_alpha + 1.0f;
    float spec_alpha = sa * sa;
    float* p = g_params + b * 8;
    p[0] = t1 * 0.5f + 0.5f;                  // light_a
    p[1] = t2 * 0.5f + 0.5f;                  // light_b
    p[2] = spec_alpha;
    p[3] = (t5 * 0.5f + 0.5f) * 0.5f;         // spec_strength
    float lx = light[b * 2 + 0];
    float ly = light[b * 2 + 1];
    float n = sqrtf(lx * lx + ly * ly + 1.0f);
    p[4] = lx / n;
    p[5] = ly / n;
    p[6] = 1.0f / n;
    p[7] = __powf(EPSV, spec_alpha);          // spec_sh when spec clamps to EPS
    g_min_bits[b] = 0x7f7fffff;               // +FLT_MAX bits
}

// Build bilinear quad image + per-batch min-depth (positive-float atomicMin).
__global__ void __launch_bounds__(256) quad_kernel(const float* __restrict__ depth) {
    int idx = blockIdx.x * 256 + threadIdx.x;
    int b = idx >> 16;
    int p = idx & (SS - 1);
    int y = p >> 8;
    int x = p & 255;
    const float* dimg = depth + b * SS;
    int x1 = min(x + 1, 255);
    int y1 = min(y + 1, 255);
    float4 q;
    q.x = __ldg(dimg + y  * SDIM + x);
    q.y = __ldg(dimg + y  * SDIM + x1);
    q.z = __ldg(dimg + y1 * SDIM + x);
    q.w = __ldg(dimg + y1 * SDIM + x1);
    g_quad[idx] = q;

    float m = q.x;
    #pragma unroll
    for (int s = 16; s > 0; s >>= 1)
        m = fminf(m, __shfl_xor_sync(0xffffffffu, m, s));
    __shared__ float warp_min[8];
    if ((threadIdx.x & 31) == 0) warp_min[threadIdx.x >> 5] = m;
    __syncthreads();
    if (threadIdx.x == 0) {
        float bm = warp_min[0];
        #pragma unroll
        for (int w = 1; w < 8; w++) bm = fminf(bm, warp_min[w]);
        atomicMin(&g_min_bits[b], __float_as_int(bm));   // valid: all positive
    }
}

// Per-ray setup shared by march kernels.
struct Ray {
    float d, sz, sxW, syW, pxW0, pyW0, nf;
};
__device__ __forceinline__ Ray ray_setup(int idx) {
    int b = idx >> 16;
    int p = idx & (SS - 1);
    int i = p >> 8;
    int j = p & 255;
    float d = __ldg(&g_quad[idx].x);            // quad.x == depth[p]
    float ci = __fmul_rn(__fadd_rn(__fmul_rn((float)i, 2.0f / 255.0f), -1.0f), T_FOV);
    float cj = __fmul_rn(__fadd_rn(__fmul_rn((float)j, 2.0f / 255.0f), -1.0f), T_FOV);
    const float* prm = g_params + b * 8;
    Ray r;
    r.d = d;
    float sx = -prm[4] * (1.0f / 256.0f);
    float sy = -prm[5] * (1.0f / 256.0f);
    r.sz = -prm[6] * (1.0f / 256.0f);           // strictly negative
    r.sxW = sx * WSC;
    r.syW = sy * WSC;
    r.pxW0 = cj * d * WSC;
    r.pyW0 = ci * d * WSC;
    float minz = __int_as_float(g_min_bits[b]) - 1e-5f;
    // Steps with pz >= minz: any bilinear sample is a convex combination of
    // depths >= min_depth, so shadow is impossible once pz < minz.
    r.nf = fminf(floorf((d - minz) * __fdividef(-1.0f, r.sz)), 256.0f);
    return r;
}

// N march steps kk = kb..kb+N-1 (no n-clamp: steps past n provably cannot
// produce a false hit — pzz < minz <= all depths — and coords are
// NaN/overflow-safe via the [0,255] clamp). One RCP at the chunk center;
// rz via 3rd-order Horner (|e| <= (N/2)*0.0075, trunc error negligible).
template <int N>
__device__ __forceinline__ bool marchN(float kb, const Ray& r,
                                       const float4* __restrict__ quad) {
    float mid = 0.5f * (float)(N - 1);
    float pzm = fmaf(kb + mid, r.sz, r.d);
    float rzm = __fdividef(1.0f, pzm);
    float c = r.sz * rzm;
    bool hit = false;
    #pragma unroll
    for (int u = 0; u < N; u++) {
        float kk = kb + (float)u;               // compile-time offset
        float e = ((float)u - mid) * c;
        float t1 = 1.0f - e;
        float t2 = fmaf(-e, t1, 1.0f);
        float pl = fmaf(-e, t2, 1.0f);          // 1 - e + e^2 - e^3
        float rz = rzm * pl;
        float pzz = fmaf(kk, r.sz, r.d);
        float x = fmaf(fmaf(kk, r.sxW, r.pxW0), rz, 127.5f);
        float y = fmaf(fmaf(kk, r.syW, r.pyW0), rz, 127.5f);
        x = fminf(fmaxf(x, 0.0f), 255.0f);      // also maps NaN -> 0
        y = fminf(fmaxf(y, 0.0f), 255.0f);
        int x0i = __float2int_rd(x);
        int y0i = __float2int_rd(y);
        float wx = x - (float)x0i;
        float wy = y - (float)y0i;
        float4 q = __ldg(quad + y0i * SDIM + x0i);
        float top = fmaf(wx, q.y - q.x, q.x);
        float bot = fmaf(wx, q.w - q.z, q.z);
        float sampled = fmaf(wy, bot - top, top);
        hit |= (sampled < pzz);
    }
    return hit;
}

// Phase 1: steps 1..8; warp-uniform check; steps 9..16 only if some lane
// still needs them. Survivors -> per-batch queue (block spans one batch).
__global__ void __launch_bounds__(256) shadow1_kernel() {
    int idx = blockIdx.x * blockDim.x + threadIdx.x;
    int b = idx >> 16;
    const float4* quad = g_quad + (idx & ~(SS - 1));
    Ray r = ray_setup(idx);

    bool hit = marchN<8>(1.0f, r, quad);
    bool need2 = !hit && (r.nf > 8.0f);
    if (__any_sync(0xffffffffu, need2))
        hit |= marchN<8>(9.0f, r, quad);
    g_shadow[idx] = hit ? 1.0f : 0.0f;

    // Warp-aggregated push into this batch's queue segment
    bool surv = !hit && (r.nf > (float)P1_STEPS);
    unsigned mask = __ballot_sync(0xffffffffu, surv);
    if (mask) {
        int lane = threadIdx.x & 31;
        int leader = __ffs(mask) - 1;
        int base = 0;
        if (lane == leader) base = atomicAdd(&g_qcountA[b], __popc(mask));
        base = __shfl_sync(0xffffffffu, base, leader);
        if (surv)
            g_queueA[b * SS + base + __popc(mask & ((1u << lane) - 1u))] = idx;
    }
}

// Phase 2: per-batch dense tail march from k = 17, check every 16 steps.
// blockIdx.y = batch -> all lanes sample the same quad image.
__global__ void __launch_bounds__(256) shadow2_kernel() {
    int b = blockIdx.y;
    int total = g_qcountA[b];
    const int stride = gridDim.x * blockDim.x;
    for (int q = blockIdx.x * blockDim.x + threadIdx.x; q < total; q += stride) {
        int idx = g_queueA[b * SS + q];
        const float4* quad = g_quad + (idx & ~(SS - 1));
        Ray r = ray_setup(idx);
        bool hit = false;
        for (float kb = (float)(P1_STEPS + 1); kb <= r.nf && !hit; kb += 16.0f) {
            hit  = marchN<8>(kb,        r, quad);
            hit |= marchN<8>(kb + 8.0f, r, quad);
        }
        if (hit) g_shadow[idx] = 1.0f;
    }
}

// Fused: 7x7 separable Gaussian blur of shadow (smem tile) + Phong epilogue.
__global__ void __launch_bounds__(1024) final_kernel(const float* __restrict__ netA,
                                                     const float* __restrict__ normal,
                                                     float* __restrict__ out) {
    __shared__ float s_sh[38][40];
    __shared__ float s_hb[38][33];

    int b = blockIdx.z;
    int ti0 = blockIdx.y * 32;
    int tj0 = blockIdx.x * 32;
    int tx = threadIdx.x;
    int ty = threadIdx.y;
    int tid = ty * 32 + tx;

    const float* shb = g_shadow + b * SS;

    for (int t = tid; t < 38 * 38; t += 1024) {
        int r = t / 38;
        int c = t - r * 38;
        int gi = ti0 - 3 + r;
        int gj = tj0 - 3 + c;
        float v = 0.0f;
        if (gi >= 0 && gi < SDIM && gj >= 0 && gj < SDIM) v = shb[gi * SDIM + gj];
        s_sh[r][c] = v;
    }
    __syncthreads();

    for (int t = tid; t < 38 * 32; t += 1024) {
        int r = t >> 5;
        int c = t & 31;
        float acc = 0.0f;
        #pragma unroll
        for (int dj = 0; dj < 7; dj++) acc += GW[dj] * s_sh[r][c + dj];
        s_hb[r][c] = acc;
    }
    __syncthreads();

    float ssum = 0.0f;
    #pragma unroll
    for (int dy = 0; dy < 7; dy++) ssum += GW[dy] * s_hb[ty + dy][tx];
    float shadow_factor = fminf(fmaxf(1.0f - ssum, 0.1f), 1.0f);

    int i = ti0 + ty;
    int j = tj0 + tx;
    int p = i * SDIM + j;

    const float* prm = g_params + b * 8;
    float la = prm[0], lb = prm[1], spec_alpha = prm[2], spec_strength = prm[3];
    float ldx = prm[4], ldy = prm[5], ldz = prm[6], eps_pow = prm[7];

    const float* nb = normal + b * 3 * SS;
    float nx = __ldg(nb + p);
    float ny = __ldg(nb + SS + p);
    float nz = __ldg(nb + 2 * SS + p);

    float cosb = nx * ldx + ny * ldy + nz * ldz;
    float diffuse = fmaxf(cosb, 0.0f);

    float aj = __fmul_rn(__fadd_rn(__fmul_rn((float)(255 - j), 2.0f / 255.0f), -1.0f), T_FOV);
    float ai = __fmul_rn(__fadd_rn(__fmul_rn((float)(255 - i), 2.0f / 255.0f), -1.0f), T_FOV);
    float rnrm = rsqrtf(ai * ai + aj * aj + 1.0f);
    float vdx = aj * rnrm, vdy = ai * rnrm, vdz = rnrm;

    float rdx = 2.0f * cosb * nx - ldx;
    float rdy = 2.0f * cosb * ny - ldy;
    float rdz = 2.0f * cosb * nz - ldz;

    float mask = (i >= 5 && i < SDIM - 5 && j >= 5 && j < SDIM - 5) ? 1.0f : 0.0f;
    float spec = fmaxf(vdx * rdx + vdy * rdy + vdz * rdz, 0.0f)
               * ((cosb > 0.0f) ? 1.0f : 0.0f) * mask;
    float spec_sh = (spec > EPSV)
                  ? __powf(fminf(spec, ONE_M_EPS), spec_alpha)
                  : eps_pow;

    float shading = la + lb * diffuse * shadow_factor;
    float term2 = spec_strength * lb * spec_sh;

    const float NLOG2E2 = -2.8853900817779268f;   // -2*log2(e)
    const float* ab = netA + b * 5 * SS;
    float* ob = out + b * 3 * SS;
    #pragma unroll
    for (int c = 0; c < 3; c++) {
        float a = __ldg(ab + c * SS + p);
        float u = exp2f(a * NLOG2E2);
        float alb = exp2f(-GAMMA_F * __log2f(1.0f + u));
        float r = alb * shading + term2;
        ob[c * SS + p] = __powf(fmaxf(r, EPSV), INV_GAMMA);
    }
}

extern "C" void kernel_launch(void* const* d_in, const int* in_sizes, int n_in,
                              void* d_out, int out_size) {
    const float* netA   = (const float*)d_in[0];
    const float* netL   = (const float*)d_in[1];
    const float* normal = (const float*)d_in[2];
    const float* depth  = (const float*)d_in[3];
    const float* light  = (const float*)d_in[4];
    float* out = (float*)d_out;

    params_kernel<<<1, 32>>>(netL, light);
    quad_kernel<<<TOT / 256, 256>>>(depth);
    shadow1_kernel<<<TOT / 256, 256>>>();
    dim3 g2(37, NB);                    // 37*32 = 1184 blocks, batch-partitioned
    shadow2_kernel<<<g2, 256>>>();
    dim3 grid(SDIM / 32, SDIM / 32, NB);
    dim3 blk(32, 32);
    final_kernel<<<grid, blk>>>(netA, normal, out);
}

// round 15
// speedup vs baseline: 1.1813x; 1.1516x over previous
#include <cuda_runtime.h>
#include <math.h>

#define NB 32
#define SDIM 256
#define SS 65536            // SDIM*SDIM
#define TOT (NB*SS)

#define T_FOV 0.08748866352592401f   // tan(10/360*pi)
#define EPSV 1e-7f
#define ONE_M_EPS 0.99999990f        // float(1.0 - 1e-7)
#define INV_GAMMA 0.45454545454545453f
#define GAMMA_F 2.2f
#define P1_STEPS 16                  // phase-1 cap (per-lane exit, cadence 8)
#define WSC (128.0f / T_FOV)         // pixel-projection scale

// Scratch (no allocations allowed)
static __device__ float g_params[NB * 12];  // see params_kernel
static __device__ int   g_min_bits[NB];     // min depth as positive-float bits
static __device__ float g_shadow[TOT];
static __device__ float4 g_quad[TOT];       // (v00, v01, v10, v11) border-clamped, 32MB
static __device__ int   g_queue[TOT];       // survivor ray indices (global)
static __device__ int   g_qcount;

// Normalized 1D Gaussian weights (ksize=7, sigma=2); separable form of the
// reference's outer(g,g)/sum 2D kernel.
__constant__ float GW[7] = {0.07015933f, 0.13107488f, 0.19071282f,
                            0.21610594f,
                            0.19071282f, 0.13107488f, 0.07015933f};

__global__ void params_kernel(const float* __restrict__ netL,
                              const float* __restrict__ light) {
    int b = threadIdx.x;
    if (b == 0) g_qcount = 0;
    if (b >= NB) return;
    float t0 = tanhf(netL[b * 6 + 0]);
    float t1 = tanhf(netL[b * 6 + 1]);
    float t2 = tanhf(netL[b * 6 + 2]);
    float t5 = tanhf(netL[b * 6 + 5]);
    const float t_alpha = 10.313708498984761f;   // sqrt(128) - 1
    float sa = (t0 * 0.5f + 0.5f) * t_alpha + 1.0f;
    float spec_alpha = sa * sa;
    float* p = g_params + b * 12;
    p[0] = t1 * 0.5f + 0.5f;                  // light_a
    p[1] = t2 * 0.5f + 0.5f;                  // light_b
    p[2] = spec_alpha;
    p[3] = (t5 * 0.5f + 0.5f) * 0.5f;         // spec_strength
    float lx = light[b * 2 + 0];
    float ly = light[b * 2 + 1];
    float n = sqrtf(lx * lx + ly * ly + 1.0f);
    p[4] = lx / n;                            // ldx
    p[5] = ly / n;                            // ldy
    p[6] = 1.0f / n;                          // ldz
    p[7] = __powf(EPSV, spec_alpha);          // spec_sh when spec clamps to EPS
    // Moebius projection constants: x(k) = Ax + Bx/pz(k), Ax = W * (ldx/ldz) = W * lx
    p[8] = WSC * lx;                          // Ax
    p[9] = WSC * ly;                          // Ay
    g_min_bits[b] = 0x7f7fffff;               // +FLT_MAX bits
}

// Build bilinear quad image + per-batch min-depth (positive-float atomicMin).
__global__ void __launch_bounds__(256) quad_kernel(const float* __restrict__ depth) {
    int idx = blockIdx.x * 256 + threadIdx.x;
    int b = idx >> 16;
    int p = idx & (SS - 1);
    int y = p >> 8;
    int x = p & 255;
    const float* dimg = depth + b * SS;
    int x1 = min(x + 1, 255);
    int y1 = min(y + 1, 255);
    float4 q;
    q.x = __ldg(dimg + y  * SDIM + x);
    q.y = __ldg(dimg + y  * SDIM + x1);
    q.z = __ldg(dimg + y1 * SDIM + x);
    q.w = __ldg(dimg + y1 * SDIM + x1);
    g_quad[idx] = q;

    float m = q.x;
    #pragma unroll
    for (int s = 16; s > 0; s >>= 1)
        m = fminf(m, __shfl_xor_sync(0xffffffffu, m, s));
    __shared__ float warp_min[8];
    if ((threadIdx.x & 31) == 0) warp_min[threadIdx.x >> 5] = m;
    __syncthreads();
    if (threadIdx.x == 0) {
        float bm = warp_min[0];
        #pragma unroll
        for (int w = 1; w < 8; w++) bm = fminf(bm, warp_min[w]);
        atomicMin(&g_min_bits[b], __float_as_int(bm));   // valid: all positive
    }
}

// Per-ray setup. Projection in Moebius form:
//   x(k) = Ax + Bx * rz,  rz = 1/pz(k),  pz(k) = d + k*sz
//   Ax = W*lx (per batch),  Bx = d*(cj*W - Ax)
// (algebraically identical to ((cj*d + k*sx)/pz)*W).
struct Ray {
    float d, sz, Ax, Ay, Bx, By, nf;
};
__device__ __forceinline__ Ray ray_setup(int idx) {
    int b = idx >> 16;
    int p = idx & (SS - 1);
    int i = p >> 8;
    int j = p & 255;
    float d = __ldg(&g_quad[idx].x);            // quad.x == depth[p]
    float ci = __fmul_rn(__fadd_rn(__fmul_rn((float)i, 2.0f / 255.0f), -1.0f), T_FOV);
    float cj = __fmul_rn(__fadd_rn(__fmul_rn((float)j, 2.0f / 255.0f), -1.0f), T_FOV);
    const float* prm = g_params + b * 12;
    Ray r;
    r.d = d;
    r.sz = -prm[6] * (1.0f / 256.0f);           // strictly negative
    r.Ax = prm[8];
    r.Ay = prm[9];
    r.Bx = d * (cj * WSC - r.Ax);
    r.By = d * (ci * WSC - r.Ay);
    float minz = __int_as_float(g_min_bits[b]) - 1e-5f;
    // Steps with pz >= minz: any bilinear sample is a convex combination of
    // depths >= min_depth, so shadow is impossible once pz < minz.
    r.nf = fminf(floorf((d - minz) * __fdividef(-1.0f, r.sz)), 256.0f);
    return r;
}

// N march steps kk = kb..kb+N-1 (no n-clamp: steps past n provably cannot
// produce a false hit — pzz < minz <= all depths — and coords are
// NaN/overflow-safe via the [0,255] clamp). One RCP at the chunk center;
// rz = rzm*(1 - e + e^2 - e^3), e = (u-mid)*sz*rzm (trunc err ~ e^4, negligible).
// The Horner poly is shared by x and y via gx = Bx*rzm, gy = By*rzm.
template <int N>
__device__ __forceinline__ bool marchN(float kb, const Ray& r,
                                       const float4* __restrict__ quad) {
    const float mid = 0.5f * (float)(N - 1);
    float pzm = fmaf(kb + mid, r.sz, r.d);
    float rzm = __fdividef(1.0f, pzm);
    float c = r.sz * rzm;
    float gx = r.Bx * rzm;
    float gy = r.By * rzm;
    bool hit = false;
    #pragma unroll
    for (int u = 0; u < N; u++) {
        float e = ((float)u - mid) * c;         // compile-time (u-mid)
        float t1 = 1.0f - e;
        float t2 = fmaf(-e, t1, 1.0f);
        float pl = fmaf(-e, t2, 1.0f);          // 1 - e + e^2 - e^3
        float x = fmaf(gx, pl, r.Ax - 0.0f) + 127.5f;
        float y = fmaf(gy, pl, r.Ay - 0.0f) + 127.5f;
        float pzz = fmaf(kb + (float)u, r.sz, r.d);
        x = fminf(fmaxf(x, 0.0f), 255.0f);      // also maps NaN -> 0
        y = fminf(fmaxf(y, 0.0f), 255.0f);
        int x0i = __float2int_rd(x);
        int y0i = __float2int_rd(y);
        float wx = x - (float)x0i;
        float wy = y - (float)y0i;
        float4 q = __ldg(quad + y0i * SDIM + x0i);
        float top = fmaf(wx, q.y - q.x, q.x);
        float bot = fmaf(wx, q.w - q.z, q.z);
        float sampled = fmaf(wy, bot - top, top);
        hit |= (sampled < pzz);
    }
    return hit;
}

// Phase 1: per-lane-exit march, cadence 8, cap 16 (pixel layout, coherent).
// Survivors -> global queue (warp-aggregated push).
__global__ void __launch_bounds__(256) shadow1_kernel() {
    int idx = blockIdx.x * blockDim.x + threadIdx.x;
    const float4* quad = g_quad + (idx & ~(SS - 1));
    Ray r = ray_setup(idx);

    int ncap = (int)fminf(r.nf, (float)P1_STEPS);
    float sh = 0.0f;
    for (int k = 1; k <= ncap && sh == 0.0f; k += 8) {
        if (marchN<8>((float)k, r, quad)) sh = 1.0f;
    }
    g_shadow[idx] = sh;

    bool surv = (sh == 0.0f) && (r.nf > (float)P1_STEPS);
    unsigned mask = __ballot_sync(0xffffffffu, surv);
    if (mask) {
        int lane = threadIdx.x & 31;
        int leader = __ffs(mask) - 1;
        int base = 0;
        if (lane == leader) base = atomicAdd(&g_qcount, __popc(mask));
        base = __shfl_sync(0xffffffffu, base, leader);
        if (surv) g_queue[base + __popc(mask & ((1u << lane) - 1u))] = idx;
    }
}

// Phase 2: global-queue dense tail march from k = 17, check every 16 steps
// (self-balancing grid-stride; best measured tail config).
__global__ void __launch_bounds__(256) shadow2_kernel() {
    int total = g_qcount;
    for (int q = blockIdx.x * blockDim.x + threadIdx.x; q < total;
         q += gridDim.x * blockDim.x) {
        int idx = g_queue[q];
        const float4* quad = g_quad + (idx & ~(SS - 1));
        Ray r = ray_setup(idx);
        bool hit = false;
        for (float kb = (float)(P1_STEPS + 1); kb <= r.nf && !hit; kb += 16.0f) {
            hit  = marchN<8>(kb,        r, quad);
            hit |= marchN<8>(kb + 8.0f, r, quad);
        }
        if (hit) g_shadow[idx] = 1.0f;
    }
}

// Fused: 7x7 separable Gaussian blur of shadow (smem tile) + Phong epilogue.
__global__ void __launch_bounds__(1024) final_kernel(const float* __restrict__ netA,
                                                     const float* __restrict__ normal,
                                                     float* __restrict__ out) {
    __shared__ float s_sh[38][40];
    __shared__ float s_hb[38][33];

    int b = blockIdx.z;
    int ti0 = blockIdx.y * 32;
    int tj0 = blockIdx.x * 32;
    int tx = threadIdx.x;
    int ty = threadIdx.y;
    int tid = ty * 32 + tx;

    const float* shb = g_shadow + b * SS;

    for (int t = tid; t < 38 * 38; t += 1024) {
        int r = t / 38;
        int c = t - r * 38;
        int gi = ti0 - 3 + r;
        int gj = tj0 - 3 + c;
        float v = 0.0f;
        if (gi >= 0 && gi < SDIM && gj >= 0 && gj < SDIM) v = shb[gi * SDIM + gj];
        s_sh[r][c] = v;
    }
    __syncthreads();

    for (int t = tid; t < 38 * 32; t += 1024) {
        int r = t >> 5;
        int c = t & 31;
        float acc = 0.0f;
        #pragma unroll
        for (int dj = 0; dj < 7; dj++) acc += GW[dj] * s_sh[r][c + dj];
        s_hb[r][c] = acc;
    }
    __syncthreads();

    float ssum = 0.0f;
    #pragma unroll
    for (int dy = 0; dy < 7; dy++) ssum += GW[dy] * s_hb[ty + dy][tx];
    float shadow_factor = fminf(fmaxf(1.0f - ssum, 0.1f), 1.0f);

    int i = ti0 + ty;
    int j = tj0 + tx;
    int p = i * SDIM + j;

    const float* prm = g_params + b * 12;
    float la = prm[0], lb = prm[1], spec_alpha = prm[2], spec_strength = prm[3];
    float ldx = prm[4], ldy = prm[5], ldz = prm[6], eps_pow = prm[7];

    const float* nb = normal + b * 3 * SS;
    float nx = __ldg(nb + p);
    float ny = __ldg(nb + SS + p);
    float nz = __ldg(nb + 2 * SS + p);

    float cosb = nx * ldx + ny * ldy + nz * ldz;
    float diffuse = fmaxf(cosb, 0.0f);

    float aj = __fmul_rn(__fadd_rn(__fmul_rn((float)(255 - j), 2.0f / 255.0f), -1.0f), T_FOV);
    float ai = __fmul_rn(__fadd_rn(__fmul_rn((float)(255 - i), 2.0f / 255.0f), -1.0f), T_FOV);
    float rnrm = rsqrtf(ai * ai + aj * aj + 1.0f);
    float vdx = aj * rnrm, vdy = ai * rnrm, vdz = rnrm;

    float rdx = 2.0f * cosb * nx - ldx;
    float rdy = 2.0f * cosb * ny - ldy;
    float rdz = 2.0f * cosb * nz - ldz;

    float mask = (i >= 5 && i < SDIM - 5 && j >= 5 && j < SDIM - 5) ? 1.0f : 0.0f;
    float spec = fmaxf(vdx * rdx + vdy * rdy + vdz * rdz, 0.0f)
               * ((cosb > 0.0f) ? 1.0f : 0.0f) * mask;
    float spec_sh = (spec > EPSV)
                  ? __powf(fminf(spec, ONE_M_EPS), spec_alpha)
                  : eps_pow;

    float shading = la + lb * diffuse * shadow_factor;
    float term2 = spec_strength * lb * spec_sh;

    const float NLOG2E2 = -2.8853900817779268f;   // -2*log2(e)
    const float* ab = netA + b * 5 * SS;
    float* ob = out + b * 3 * SS;
    #pragma unroll
    for (int c = 0; c < 3; c++) {
        float a = __ldg(ab + c * SS + p);
        float u = exp2f(a * NLOG2E2);
        float alb = exp2f(-GAMMA_F * __log2f(1.0f + u));
        float r = alb * shading + term2;
        ob[c * SS + p] = __powf(fmaxf(r, EPSV), INV_GAMMA);
    }
}

extern "C" void kernel_launch(void* const* d_in, const int* in_sizes, int n_in,
                              void* d_out, int out_size) {
    const float* netA   = (const float*)d_in[0];
    const float* netL   = (const float*)d_in[1];
    const float* normal = (const float*)d_in[2];
    const float* depth  = (const float*)d_in[3];
    const float* light  = (const float*)d_in[4];
    float* out = (float*)d_out;

    params_kernel<<<1, 32>>>(netL, light);
    quad_kernel<<<TOT / 256, 256>>>(depth);
    shadow1_kernel<<<TOT / 256, 256>>>();
    shadow2_kernel<<<1184, 256>>>();   // global queue, self-balancing
    dim3 grid(SDIM / 32, SDIM / 32, NB);
    dim3 blk(32, 32);
    final_kernel<<<grid, blk>>>(netA, normal, out);
}